// round 1
// baseline (speedup 1.0000x reference)
#include <cuda_runtime.h>
#include <cstdint>
#include <math.h>

// Problem constants
#define NHEADS 12
#define NWIN   1152
#define NTOK   64
#define CDIM   384
#define DH     32
#define MROWS  (NWIN * NTOK)   // 73728

// ---------------------------------------------------------------------------
// Device-global scratch (no cudaMalloc allowed)
// ---------------------------------------------------------------------------
__device__ float g_Q [MROWS * CDIM];
__device__ float g_K [MROWS * CDIM];
__device__ float g_V [MROWS * CDIM];
__device__ float g_AO[MROWS * CDIM];
__device__ float g_tb[225 * NHEADS];   // CPB MLP output (225 rel positions x heads)
__device__ float g_ls[NHEADS];         // logit scale per head

// ---------------------------------------------------------------------------
// Kernel 1: continuous position bias MLP: tb[225][12], logit scale
// grid = 225 blocks (one per relative-position table row), 128 threads
// ---------------------------------------------------------------------------
__global__ void cpb_kernel(const float* __restrict__ w1, const float* __restrict__ b1,
                           const float* __restrict__ w2, const float* __restrict__ b2,
                           const float* __restrict__ tau)
{
    __shared__ float red[128][12];
    const int m   = blockIdx.x;      // 0..224
    const int tid = threadIdx.x;
    const int ai  = m / 15;          // index along dim with rw values
    const int bi  = m % 15;          // index along dim with rh values

    // table[ai][bi] = (f(bi-7), f(ai-7)) with f(x) = sign(x)*log2(|x|*8/7+1)/3
    float x0 = (float)(bi - 7) * (8.0f / 7.0f);
    float x1 = (float)(ai - 7) * (8.0f / 7.0f);
    float s0 = (x0 > 0.f) ? 1.f : ((x0 < 0.f) ? -1.f : 0.f);
    float s1 = (x1 > 0.f) ? 1.f : ((x1 < 0.f) ? -1.f : 0.f);
    float v0 = s0 * log2f(fabsf(x0) + 1.0f) * (1.0f / 3.0f);
    float v1 = s1 * log2f(fabsf(x1) + 1.0f) * (1.0f / 3.0f);

    float p[NHEADS];
    #pragma unroll
    for (int h = 0; h < NHEADS; h++) p[h] = 0.f;

    for (int c = tid; c < 512; c += 128) {
        float hv = v0 * w1[c] + v1 * w1[512 + c] + b1[c];
        hv = fmaxf(hv, 0.0f);
        #pragma unroll
        for (int h = 0; h < NHEADS; h++) p[h] += hv * w2[c * NHEADS + h];
    }
    #pragma unroll
    for (int h = 0; h < NHEADS; h++) red[tid][h] = p[h];
    __syncthreads();

    if (tid < NHEADS) {
        float s = 0.f;
        for (int t2 = 0; t2 < 128; t2++) s += red[t2][tid];
        g_tb[m * NHEADS + tid] = s + b2[tid];
        if (m == 0) {
            g_ls[tid] = fmaxf(tau[tid] + 2.302585092994046f, 0.01f); // ln(10)
        }
    }
}

// ---------------------------------------------------------------------------
// 3xTF32 split helper + mma wrapper
// ---------------------------------------------------------------------------
__device__ __forceinline__ void split_tf32(float x, uint32_t& hi, uint32_t& lo)
{
    uint32_t h;
    asm("cvt.rna.tf32.f32 %0, %1;" : "=r"(h) : "f"(x));
    float hf = __uint_as_float(h);
    float lf = x - hf;
    uint32_t l;
    asm("cvt.rna.tf32.f32 %0, %1;" : "=r"(l) : "f"(lf));
    hi = h; lo = l;
}

__device__ __forceinline__ void mma_tf32(float c[4], const uint32_t a[4], const uint32_t b[2])
{
    asm volatile(
        "mma.sync.aligned.m16n8k8.row.col.f32.tf32.tf32.f32 "
        "{%0,%1,%2,%3},{%4,%5,%6,%7},{%8,%9},{%0,%1,%2,%3};"
        : "+f"(c[0]), "+f"(c[1]), "+f"(c[2]), "+f"(c[3])
        : "r"(a[0]), "r"(a[1]), "r"(a[2]), "r"(a[3]), "r"(b[0]), "r"(b[1]));
}

// ---------------------------------------------------------------------------
// Kernel 2: generic C[M,384] = A[M,384] @ W[384,384] (+ bias), 3xTF32
// Block tile 128x64, BK=16, 8 warps (4 x 2), warp tile 32x32.
// grid = (M/128, 384/64), block = 256
// ---------------------------------------------------------------------------
__global__ __launch_bounds__(256) void gemm384_kernel(
    const float* __restrict__ A, const float* __restrict__ W,
    const float* __restrict__ bias, float* __restrict__ C)
{
    __shared__ float As[128][20];  // padded: conflict-free fragment loads
    __shared__ float Ws[16][72];   // padded

    const int tid  = threadIdx.x;
    const int lane = tid & 31;
    const int warp = tid >> 5;
    const int wm   = warp >> 1;    // 0..3
    const int wn   = warp & 1;     // 0..1
    const int rb   = blockIdx.x * 128;
    const int cb   = blockIdx.y * 64;
    const int g    = lane >> 2;    // 0..7
    const int t    = lane & 3;     // 0..3

    float acc[2][4][4];
    #pragma unroll
    for (int mi = 0; mi < 2; mi++)
        #pragma unroll
        for (int ni = 0; ni < 4; ni++)
            #pragma unroll
            for (int q = 0; q < 4; q++) acc[mi][ni][q] = 0.f;

    for (int k0 = 0; k0 < 384; k0 += 16) {
        // Load A tile (128 x 16)
        #pragma unroll
        for (int i = 0; i < 2; i++) {
            int idx = tid + i * 256;
            int r = idx >> 2;
            int c = (idx & 3) << 2;
            float4 v = *reinterpret_cast<const float4*>(&A[(size_t)(rb + r) * 384 + k0 + c]);
            As[r][c + 0] = v.x; As[r][c + 1] = v.y; As[r][c + 2] = v.z; As[r][c + 3] = v.w;
        }
        // Load W tile (16 x 64)
        {
            int r = tid >> 4;
            int c = (tid & 15) << 2;
            float4 v = *reinterpret_cast<const float4*>(&W[(size_t)(k0 + r) * 384 + cb + c]);
            *reinterpret_cast<float4*>(&Ws[r][c]) = v;
        }
        __syncthreads();

        #pragma unroll
        for (int ks = 0; ks < 2; ks++) {
            uint32_t ahi[2][4], alo[2][4];
            #pragma unroll
            for (int mi = 0; mi < 2; mi++) {
                int r0 = wm * 32 + mi * 16 + g;
                int c0 = ks * 8 + t;
                split_tf32(As[r0    ][c0    ], ahi[mi][0], alo[mi][0]);
                split_tf32(As[r0 + 8][c0    ], ahi[mi][1], alo[mi][1]);
                split_tf32(As[r0    ][c0 + 4], ahi[mi][2], alo[mi][2]);
                split_tf32(As[r0 + 8][c0 + 4], ahi[mi][3], alo[mi][3]);
            }
            uint32_t bhi[4][2], blo[4][2];
            #pragma unroll
            for (int ni = 0; ni < 4; ni++) {
                int kk = ks * 8 + t;
                int nn = wn * 32 + ni * 8 + g;
                split_tf32(Ws[kk    ][nn], bhi[ni][0], blo[ni][0]);
                split_tf32(Ws[kk + 4][nn], bhi[ni][1], blo[ni][1]);
            }
            #pragma unroll
            for (int mi = 0; mi < 2; mi++)
                #pragma unroll
                for (int ni = 0; ni < 4; ni++) {
                    mma_tf32(acc[mi][ni], ahi[mi], blo[ni]);
                    mma_tf32(acc[mi][ni], alo[mi], bhi[ni]);
                    mma_tf32(acc[mi][ni], ahi[mi], bhi[ni]);
                }
        }
        __syncthreads();
    }

    // Epilogue
    #pragma unroll
    for (int mi = 0; mi < 2; mi++) {
        #pragma unroll
        for (int ni = 0; ni < 4; ni++) {
            int r  = rb + wm * 32 + mi * 16 + g;
            int cc = cb + wn * 32 + ni * 8 + t * 2;
            float b0 = bias ? bias[cc]     : 0.f;
            float b1 = bias ? bias[cc + 1] : 0.f;
            C[(size_t)r * 384 + cc]           = acc[mi][ni][0] + b0;
            C[(size_t)r * 384 + cc + 1]       = acc[mi][ni][1] + b1;
            C[(size_t)(r + 8) * 384 + cc]     = acc[mi][ni][2] + b0;
            C[(size_t)(r + 8) * 384 + cc + 1] = acc[mi][ni][3] + b1;
        }
    }
}

// ---------------------------------------------------------------------------
// Kernel 3: per-(window, head) cosine attention + CPB bias + mask + softmax + AV
// grid = (1152, 12), block = 128
// ---------------------------------------------------------------------------
__global__ __launch_bounds__(128) void attn_kernel(const float* __restrict__ mask)
{
    __shared__ float qs [NTOK * DH];
    __shared__ float kss[NTOK * DH];
    __shared__ float vss[NTOK * DH];
    __shared__ float at [NTOK * 65];      // padded rows
    __shared__ float qn [NTOK];
    __shared__ float kn [NTOK];
    __shared__ float tbs[225];

    const int b   = blockIdx.x;
    const int h   = blockIdx.y;
    const int tid = threadIdx.x;
    const size_t base = (size_t)b * NTOK * CDIM + h * DH;

    for (int idx = tid; idx < 512; idx += 128) {
        int n = idx >> 3;
        int d = (idx & 7) << 2;
        size_t ga = base + (size_t)n * CDIM + d;
        *reinterpret_cast<float4*>(&qs [n * DH + d]) = *reinterpret_cast<const float4*>(&g_Q[ga]);
        *reinterpret_cast<float4*>(&kss[n * DH + d]) = *reinterpret_cast<const float4*>(&g_K[ga]);
        *reinterpret_cast<float4*>(&vss[n * DH + d]) = *reinterpret_cast<const float4*>(&g_V[ga]);
    }
    for (int i = tid; i < 225; i += 128) tbs[i] = g_tb[i * NHEADS + h];
    const float ls = g_ls[h];
    __syncthreads();

    // norms
    if (tid < 64) {
        float s = 0.f;
        #pragma unroll
        for (int d = 0; d < DH; d++) { float q = qs[tid * DH + d]; s += q * q; }
        qn[tid] = sqrtf(s);
    } else {
        int i = tid - 64;
        float s = 0.f;
        #pragma unroll
        for (int d = 0; d < DH; d++) { float k = kss[i * DH + d]; s += k * k; }
        kn[i] = sqrtf(s);
    }
    __syncthreads();

    // logits
    {
        const int i  = tid >> 1;
        const int cg = tid & 1;
        float qr[DH];
        #pragma unroll
        for (int d = 0; d < DH; d += 4) {
            float4 v = *reinterpret_cast<const float4*>(&qs[i * DH + d]);
            qr[d] = v.x; qr[d + 1] = v.y; qr[d + 2] = v.z; qr[d + 3] = v.w;
        }
        const float qni = qn[i];
        const int ri = i >> 3, ci = i & 7;
        for (int jj = 0; jj < 32; jj++) {
            int j = cg * 32 + jj;
            float a0 = 0.f, a1 = 0.f, a2 = 0.f, a3 = 0.f;
            #pragma unroll
            for (int d = 0; d < DH; d += 4) {
                float4 kv = *reinterpret_cast<const float4*>(&kss[j * DH + d]);
                a0 += qr[d] * kv.x; a1 += qr[d + 1] * kv.y;
                a2 += qr[d + 2] * kv.z; a3 += qr[d + 3] * kv.w;
            }
            float dot = (a0 + a1) + (a2 + a3);
            float den = fmaxf(qni * kn[j], 1e-6f);
            int idx = ((ri - (j >> 3)) + 7) * 15 + (ci - (j & 7)) + 7;
            float bias = 16.0f / (1.0f + __expf(-tbs[idx]));
            at[i * 65 + j] = dot / den * ls + bias;
        }
    }
    __syncthreads();

    // add mask (coalesced)
    {
        const float* mrow = mask + (size_t)b * 4096;
        for (int idx = tid; idx < 1024; idx += 128) {
            float4 mv = reinterpret_cast<const float4*>(mrow)[idx];
            int f = idx << 2;
            int i = f >> 6, j = f & 63;
            at[i * 65 + j]     += mv.x;
            at[i * 65 + j + 1] += mv.y;
            at[i * 65 + j + 2] += mv.z;
            at[i * 65 + j + 3] += mv.w;
        }
    }
    __syncthreads();

    // softmax per row
    if (tid < 64) {
        float* row = &at[tid * 65];
        float m = row[0];
        for (int j = 1; j < 64; j++) m = fmaxf(m, row[j]);
        float s = 0.f;
        for (int j = 0; j < 64; j++) { float e = __expf(row[j] - m); row[j] = e; s += e; }
        float inv = 1.0f / s;
        for (int j = 0; j < 64; j++) row[j] *= inv;
    }
    __syncthreads();

    // AV
    {
        const int i  = tid >> 1;
        const int cg = tid & 1;
        float acc[16];
        #pragma unroll
        for (int d = 0; d < 16; d++) acc[d] = 0.f;
        for (int j = 0; j < 64; j++) {
            float p = at[i * 65 + j];
            const float* vr = &vss[j * DH + cg * 16];
            #pragma unroll
            for (int dd = 0; dd < 16; dd += 4) {
                float4 v = *reinterpret_cast<const float4*>(&vr[dd]);
                acc[dd] += p * v.x; acc[dd + 1] += p * v.y;
                acc[dd + 2] += p * v.z; acc[dd + 3] += p * v.w;
            }
        }
        size_t ob = (size_t)(b * NTOK + i) * CDIM + h * DH + cg * 16;
        #pragma unroll
        for (int dd = 0; dd < 16; dd += 4) {
            float4 st; st.x = acc[dd]; st.y = acc[dd + 1]; st.z = acc[dd + 2]; st.w = acc[dd + 3];
            *reinterpret_cast<float4*>(&g_AO[ob + dd]) = st;
        }
    }
}

// ---------------------------------------------------------------------------
// Launch
// ---------------------------------------------------------------------------
extern "C" void kernel_launch(void* const* d_in, const int* in_sizes, int n_in,
                              void* d_out, int out_size)
{
    (void)in_sizes; (void)n_in; (void)out_size;
    const float* x     = (const float*)d_in[0];
    const float* mask  = (const float*)d_in[1];
    const float* wq    = (const float*)d_in[2];
    const float* bq    = (const float*)d_in[3];
    const float* wk    = (const float*)d_in[4];
    const float* wv    = (const float*)d_in[5];
    const float* bv    = (const float*)d_in[6];
    const float* cw1   = (const float*)d_in[7];
    const float* cb1   = (const float*)d_in[8];
    const float* cw2   = (const float*)d_in[9];
    const float* cb2   = (const float*)d_in[10];
    const float* tau   = (const float*)d_in[11];
    const float* wproj = (const float*)d_in[12];
    const float* bproj = (const float*)d_in[13];
    float* out = (float*)d_out;

    float *pQ, *pK, *pV, *pAO;
    cudaGetSymbolAddress((void**)&pQ,  g_Q);
    cudaGetSymbolAddress((void**)&pK,  g_K);
    cudaGetSymbolAddress((void**)&pV,  g_V);
    cudaGetSymbolAddress((void**)&pAO, g_AO);

    cpb_kernel<<<225, 128>>>(cw1, cb1, cw2, cb2, tau);

    dim3 gg(MROWS / 128, CDIM / 64);
    gemm384_kernel<<<gg, 256>>>(x, wq, bq,      pQ);
    gemm384_kernel<<<gg, 256>>>(x, wk, nullptr, pK);
    gemm384_kernel<<<gg, 256>>>(x, wv, bv,      pV);

    attn_kernel<<<dim3(NWIN, NHEADS), 128>>>(mask);

    gemm384_kernel<<<gg, 256>>>(pAO, wproj, bproj, out);
}